// round 13
// baseline (speedup 1.0000x reference)
#include <cuda_runtime.h>
#include <cuda_fp16.h>
#include <cstdint>

// ===========================================================================
// TensorTrainProjection via dense operator + single fp16 tensor-core GEMM.
//   W[d,j] = TT-contraction of 9 cores (2048 x 2048)
//   out = X @ W,  X: [8192, 2048] fp32
// fp16 GEMM (K=2048), W stored * 2^-8 (exact), epilogue * 256.
// Round-13: TWO launches.
//   0: pre_all (8320 blocks, 32KB smem):
//        blocks 0..127   - W build for one jh each (per-jh fixed-bottom chain
//                          cores 0-4 -> LS transposed; R from cores 5-8;
//                          combine + fp16 quant, pre-swizzled store).
//                          Cores read from gmem (4KB each, L2-resident).
//        blocks 128..8319 - conv_X (fp16 pre-swizzled tiles).
//      32KB smem keeps conv occupancy at 7 CTA/SM (R10's 40KB allowed 5 and
//      had a 16-way bank conflict; both fixed).
//   1: GEMM - R7/R11 kernel verbatim (measured best).
// Per-jh chain proven bit-identical in R10 -> rel_err must stay 2.934e-4.
// ===========================================================================

__device__ __forceinline__ uint32_t smem_u32(const void* p) {
    uint32_t a;
    asm("{ .reg .u64 t; cvta.to.shared.u64 t, %1; cvt.u32.u64 %0, t; }" : "=r"(a) : "l"(p));
    return a;
}
__device__ __forceinline__ uint32_t swz(uint32_t o) { return o ^ ((o >> 3) & 0x70); }

__device__ __forceinline__ uint32_t h2u(__half2 v) {
    return (uint32_t)__half_as_ushort(__low2half(v)) |
           ((uint32_t)__half_as_ushort(__high2half(v)) << 16);
}
__device__ __forceinline__ uint32_t pack2h(__half a, __half b) {
    return (uint32_t)__half_as_ushort(a) | ((uint32_t)__half_as_ushort(b) << 16);
}

__device__ __forceinline__ void cp16(uint32_t dst, const void* src) {
    asm volatile("cp.async.cg.shared.global [%0], [%1], 16;" :: "r"(dst), "l"(src) : "memory");
}
__device__ __forceinline__ void cp_commit() { asm volatile("cp.async.commit_group;" ::: "memory"); }
template <int N>
__device__ __forceinline__ void cp_wait() { asm volatile("cp.async.wait_group %0;" :: "n"(N) : "memory"); }

__device__ __forceinline__ void ldsm_x4(uint32_t* r, uint32_t addr) {
    asm volatile("ldmatrix.sync.aligned.m8n8.x4.shared.b16 {%0,%1,%2,%3}, [%4];"
                 : "=r"(r[0]), "=r"(r[1]), "=r"(r[2]), "=r"(r[3]) : "r"(addr));
}
__device__ __forceinline__ void ldsm_x2(uint32_t* r, uint32_t addr) {
    asm volatile("ldmatrix.sync.aligned.m8n8.x2.shared.b16 {%0,%1}, [%2];"
                 : "=r"(r[0]), "=r"(r[1]) : "r"(addr));
}
__device__ __forceinline__ void mma16816f16(float* c, const uint32_t* a, const uint32_t* b) {
    asm volatile(
        "mma.sync.aligned.m16n8k16.row.col.f32.f16.f16.f32 "
        "{%0,%1,%2,%3}, {%4,%5,%6,%7}, {%8,%9}, {%0,%1,%2,%3};"
        : "+f"(c[0]), "+f"(c[1]), "+f"(c[2]), "+f"(c[3])
        : "r"(a[0]), "r"(a[1]), "r"(a[2]), "r"(a[3]), "r"(b[0]), "r"(b[1]));
}

// ---------------- scratch (static __device__, no allocs) --------------------
static __device__ __align__(16) unsigned char g_Xh[33554432];  // 64 mt * 32 ch * 16KB
static __device__ __align__(16) unsigned char g_Wh[8388608];   // 16 nt * 32 ch * 16KB

// ---------------- launch 0: pre_all ------------------------------------------
// BUF (8192 floats = 32KB): R0 = [0..4095], LS = [4096..6143] ([r*128+dh]),
//                           SC = [6144..8191] (chain intermediates / R scratch)
__global__ void pre_all(const float* __restrict__ x, unsigned char* __restrict__ Xh,
                        const float* __restrict__ p0, const float* __restrict__ p1,
                        const float* __restrict__ p2, const float* __restrict__ p3,
                        const float* __restrict__ p4, const float* __restrict__ p5,
                        const float* __restrict__ p6, const float* __restrict__ p7,
                        const float* __restrict__ p8, unsigned char* __restrict__ Wh)
{
    __shared__ float BUF[8192];
    int b = blockIdx.x, t = threadIdx.x;

    if (b >= 128) {
        // ---- conv_X (verified, DRAM-bound) ----
        int idx = (b - 128) * 256 + t;
        int m = idx >> 8;
        int k0 = (idx & 255) * 8;
        const float* row = x + (size_t)m * 2048 + k0;
        float4 v0 = *(const float4*)row;
        float4 v1 = *(const float4*)(row + 4);
        uint32_t off = (uint32_t)(((m >> 7) * 32 + (k0 >> 6)) << 14) + swz((m & 127) * 128 + (k0 & 63) * 2);
        uint4 pk;
        pk.x = h2u(__floats2half2_rn(v0.x, v0.y));
        pk.y = h2u(__floats2half2_rn(v0.z, v0.w));
        pk.z = h2u(__floats2half2_rn(v1.x, v1.y));
        pk.w = h2u(__floats2half2_rn(v1.z, v1.w));
        *(uint4*)(Xh + off) = pk;
        return;
    }

    // ================= W build for jh = b =================
    float* R0 = BUF;           // 4096
    float* LS = BUF + 4096;    // 2048 (transposed [r*128+dh])
    float* SC = BUF + 6144;    // 2048 scratch
    int jh = b;
    int j0 = jh >> 4;
    int b1 = (jh >> 3) & 1, b2 = (jh >> 2) & 1, b3 = (jh >> 1) & 1, b4 = jh & 1;

    // ---- phase A: fixed-bottom chain cores 0..4 (verified in R10) ----
    // A0 at SC[0..127], A1 at SC[128..383], A2 at SC[384..895],
    // A3 at SC[896..1919], A4 -> LS transposed.
    if (t < 128) {
        int d0 = t >> 4, l = t & 15;
        SC[t] = p0[(d0 * 8 + j0) * 16 + l];
    }
    __syncthreads();
    if (t < 256) {   // A1[d1*16+r]
        int d1 = t >> 4, r = t & 15;
        int a = d1 & 1, d0 = d1 >> 1;
        float acc = 0.f;
        #pragma unroll
        for (int l = 0; l < 16; ++l)
            acc = fmaf(SC[d0 * 16 + l], p1[((a * 2 + b1) * 16 + l) * 16 + r], acc);
        SC[128 + t] = acc;
    }
    __syncthreads();
    for (int i = t; i < 512; i += 256) {   // A2[d2*16+r]
        int d2 = i >> 4, r = i & 15;
        int a = d2 & 1, d1 = d2 >> 1;
        float acc = 0.f;
        #pragma unroll
        for (int l = 0; l < 16; ++l)
            acc = fmaf(SC[128 + d1 * 16 + l], p2[((a * 2 + b2) * 16 + l) * 16 + r], acc);
        SC[384 + i] = acc;
    }
    __syncthreads();
    for (int i = t; i < 1024; i += 256) {  // A3[d3*16+r]
        int d3 = i >> 4, r = i & 15;
        int a = d3 & 1, d2 = d3 >> 1;
        float acc = 0.f;
        #pragma unroll
        for (int l = 0; l < 16; ++l)
            acc = fmaf(SC[384 + d2 * 16 + l], p3[((a * 2 + b3) * 16 + l) * 16 + r], acc);
        SC[896 + i] = acc;
    }
    __syncthreads();
    for (int i = t; i < 2048; i += 256) {  // A4 -> LS[r*128 + dh] (transposed)
        int dh = i & 127, r = i >> 7;
        int a = dh & 1, d3 = dh >> 1;
        float acc = 0.f;
        #pragma unroll
        for (int l = 0; l < 16; ++l)
            acc = fmaf(SC[896 + d3 * 16 + l], p4[((a * 2 + b4) * 16 + l) * 16 + r], acc);
        LS[i] = acc;
    }
    __syncthreads();

    // ---- phase B: R from cores 8,7,6,5 (verified build_R) ----
    // X8 at SC[0..63], T7 at SC[64..319], S6 at SC[320..1343], R -> R0.
    if (t < 64) {
        int l = t >> 2, d = (t >> 1) & 1, jj = t & 1;
        SC[l * 4 + d * 2 + jj] = p8[(d * 2 + jj) * 16 + l];
    }
    __syncthreads();
    if (t < 256) {  // core 7: G[a,b,l,r] = p7[a][b][r][l] (swapped bonds)
        int l = t >> 4, dp = (t >> 2) & 3, jp = t & 3;
        int a = dp >> 1, d = dp & 1, bb = jp >> 1, jj = jp & 1;
        float acc = 0.f;
        #pragma unroll
        for (int r = 0; r < 16; ++r)
            acc = fmaf(p7[((a * 2 + bb) * 16 + r) * 16 + l], SC[r * 4 + d * 2 + jj], acc);
        SC[64 + l * 16 + dp * 4 + jp] = acc;
    }
    __syncthreads();
    for (int i = t; i < 1024; i += 256) {  // core 6
        int l = i >> 6, dp = (i >> 3) & 7, jp = i & 7;
        int a = dp >> 2, d = dp & 3, bb = jp >> 2, jj = jp & 3;
        float acc = 0.f;
        #pragma unroll
        for (int r = 0; r < 16; ++r)
            acc = fmaf(p6[((a * 2 + bb) * 16 + l) * 16 + r], SC[64 + r * 16 + d * 4 + jj], acc);
        SC[320 + l * 64 + dp * 8 + jp] = acc;
    }
    __syncthreads();
    for (int i = t; i < 4096; i += 256) {  // core 5 -> R0[l*256 + dl*16 + jl]
        int l = i >> 8, dp = (i >> 4) & 15, jp = i & 15;
        int a = dp >> 3, d = dp & 7, bb = jp >> 3, jj = jp & 7;
        float acc = 0.f;
        #pragma unroll
        for (int r = 0; r < 16; ++r)
            acc = fmaf(p5[((a * 2 + bb) * 16 + l) * 16 + r], SC[320 + r * 64 + d * 8 + jj], acc);
        R0[i] = acc;
    }
    __syncthreads();

    // ---- phase C: combine + quantize + pre-swizzled store (R12 layout) ----
    int dh = t >> 1;
    for (int jl = 0; jl < 16; ++jl) {
        int j = jh * 16 + jl;
        __half h[8];
        #pragma unroll
        for (int i = 0; i < 8; ++i) {
            int dl = (t & 1) * 8 + i;
            float acc = 0.f;
            #pragma unroll
            for (int r = 0; r < 16; ++r)
                acc = fmaf(LS[r * 128 + dh], R0[r * 256 + dl * 16 + jl], acc);
            h[i] = __float2half_rn(acc * 0.00390625f);   // * 2^-8 exact
        }
        uint4 pk;
        pk.x = pack2h(h[0], h[1]);
        pk.y = pack2h(h[2], h[3]);
        pk.z = pack2h(h[4], h[5]);
        pk.w = pack2h(h[6], h[7]);
        uint32_t off = (uint32_t)(((j >> 7) * 32 + ((t * 8) >> 6)) << 14)
                     + swz((j & 127) * 128 + ((t * 8) & 63) * 2);
        *(uint4*)(Wh + off) = pk;
    }
}

// ---------------- launch 1: fp16 GEMM (R7/R11 version, measured best) --------
static constexpr int GSTAGES = 3;
static constexpr int STAGE_BYTES = 32768;
static constexpr uint32_t GEMM_SMEM = GSTAGES * STAGE_BYTES;

__device__ __forceinline__ void issue_stage(uint32_t sb, int buf, int ck, int tid,
                                            const unsigned char* __restrict__ Xh,
                                            const unsigned char* __restrict__ Wh,
                                            int by, int bx)
{
    const unsigned char* as = Xh + (((size_t)by * 32 + ck) << 14) + tid * 16;
    const unsigned char* bs = Wh + (((size_t)bx * 32 + ck) << 14) + tid * 16;
    uint32_t dst = sb + buf * STAGE_BYTES + tid * 16;
    #pragma unroll
    for (int i = 0; i < 4; ++i) cp16(dst + i * 4096, as + i * 4096);
    #pragma unroll
    for (int i = 0; i < 4; ++i) cp16(dst + 16384 + i * 4096, bs + i * 4096);
}

__global__ void __launch_bounds__(256, 2)
tt_gemm_f16(const unsigned char* __restrict__ Xh, const unsigned char* __restrict__ Wh,
            float* __restrict__ out)
{
    extern __shared__ unsigned char smem[];
    uint32_t sb = smem_u32(smem);
    int tid = threadIdx.x, wid = tid >> 5, lane = tid & 31;
    int bx = blockIdx.x, by = blockIdx.y;

    int wm = (wid & 1) * 64;
    int wn = (wid >> 1) * 32;
    int arow = wm + (lane & 15);
    int akb  = (lane >> 4) * 16;
    int brow = wn + (lane & 7);
    int bkb  = ((lane >> 3) & 1) * 16;

    float acc[4][4][4];
    #pragma unroll
    for (int mi = 0; mi < 4; ++mi)
        #pragma unroll
        for (int ni = 0; ni < 4; ++ni)
            #pragma unroll
            for (int q = 0; q < 4; ++q) acc[mi][ni][q] = 0.f;

    #pragma unroll
    for (int s = 0; s < GSTAGES - 1; ++s) {
        issue_stage(sb, s, s, tid, Xh, Wh, by, bx);
        cp_commit();
    }

    for (int it = 0; it < 32; ++it) {
        cp_wait<GSTAGES - 2>();
        __syncthreads();

        int nxt = it + GSTAGES - 1;
        if (nxt < 32) issue_stage(sb, nxt % GSTAGES, nxt, tid, Xh, Wh, by, bx);
        cp_commit();

        uint32_t base = sb + (it % GSTAGES) * STAGE_BYTES;
        #pragma unroll
        for (int ks = 0; ks < 4; ++ks) {
            uint32_t af[4][4], bf[4][2];
            #pragma unroll
            for (int mi = 0; mi < 4; ++mi)
                ldsm_x4(af[mi], base + swz((uint32_t)((arow + mi * 16) * 128 + ks * 32 + akb)));
            #pragma unroll
            for (int ni = 0; ni < 4; ++ni)
                ldsm_x2(bf[ni], base + 16384 + swz((uint32_t)((brow + ni * 8) * 128 + ks * 32 + bkb)));
            #pragma unroll
            for (int mi = 0; mi < 4; ++mi)
                #pragma unroll
                for (int ni = 0; ni < 4; ++ni)
                    mma16816f16(acc[mi][ni], af[mi], bf[ni]);
        }
    }

    int m0 = by * 128 + wm + (lane >> 2);
    int n0 = bx * 128 + wn + (lane & 3) * 2;
    #pragma unroll
    for (int mi = 0; mi < 4; ++mi) {
        #pragma unroll
        for (int ni = 0; ni < 4; ++ni) {
            float* p = out + (size_t)(m0 + mi * 16) * 2048 + n0 + ni * 8;
            *(float2*)p = make_float2(acc[mi][ni][0] * 256.f, acc[mi][ni][1] * 256.f);
            *(float2*)(p + 8 * 2048) = make_float2(acc[mi][ni][2] * 256.f, acc[mi][ni][3] * 256.f);
        }
    }
}

// ---------------- launch ------------------------------------------------------
extern "C" void kernel_launch(void* const* d_in, const int* in_sizes, int n_in,
                              void* d_out, int out_size)
{
    (void)in_sizes; (void)n_in; (void)out_size;
    const float* x = (const float*)d_in[0];
    const float* p[9];
    for (int i = 0; i < 9; ++i) p[i] = (const float*)d_in[1 + i];

    unsigned char *Xh, *Wh;
    cudaGetSymbolAddress((void**)&Xh, g_Xh);
    cudaGetSymbolAddress((void**)&Wh, g_Wh);

    pre_all<<<8320, 256>>>(x, Xh, p[0], p[1], p[2], p[3], p[4],
                           p[5], p[6], p[7], p[8], Wh);                      // 0
    cudaFuncSetAttribute(tt_gemm_f16, cudaFuncAttributeMaxDynamicSharedMemorySize, GEMM_SMEM);
    tt_gemm_f16<<<dim3(16, 64), 256, GEMM_SMEM>>>(Xh, Wh, (float*)d_out);    // 1
}

// round 14
// speedup vs baseline: 1.0784x; 1.0784x over previous
#include <cuda_runtime.h>
#include <cuda_fp16.h>
#include <cstdint>

// ===========================================================================
// TensorTrainProjection via dense operator + single fp16 tensor-core GEMM.
//   W[d,j] = TT-contraction of 9 cores (2048 x 2048)
//   out = X @ W,  X: [8192, 2048] fp32
// fp16 GEMM (K=2048), W stored * 2^-8 (exact), epilogue * 256.
// Round-14: R12 structure (measured best 217.9us) + GEMM micro-opts:
//   - B fragments via ldsm_x4 (half the B LDSM issue slots)
//   - next-stage cp.async issued after ks=0 (off the barrier-exit path)
//   - main loop unrolled x3 (static stage addresses)
// ===========================================================================

__device__ __forceinline__ uint32_t smem_u32(const void* p) {
    uint32_t a;
    asm("{ .reg .u64 t; cvta.to.shared.u64 t, %1; cvt.u32.u64 %0, t; }" : "=r"(a) : "l"(p));
    return a;
}
__device__ __forceinline__ uint32_t swz(uint32_t o) { return o ^ ((o >> 3) & 0x70); }

__device__ __forceinline__ uint32_t h2u(__half2 v) {
    return (uint32_t)__half_as_ushort(__low2half(v)) |
           ((uint32_t)__half_as_ushort(__high2half(v)) << 16);
}
__device__ __forceinline__ uint32_t pack2h(__half a, __half b) {
    return (uint32_t)__half_as_ushort(a) | ((uint32_t)__half_as_ushort(b) << 16);
}

__device__ __forceinline__ void cp16(uint32_t dst, const void* src) {
    asm volatile("cp.async.cg.shared.global [%0], [%1], 16;" :: "r"(dst), "l"(src) : "memory");
}
__device__ __forceinline__ void cp_commit() { asm volatile("cp.async.commit_group;" ::: "memory"); }
template <int N>
__device__ __forceinline__ void cp_wait() { asm volatile("cp.async.wait_group %0;" :: "n"(N) : "memory"); }

__device__ __forceinline__ void ldsm_x4(uint32_t* r, uint32_t addr) {
    asm volatile("ldmatrix.sync.aligned.m8n8.x4.shared.b16 {%0,%1,%2,%3}, [%4];"
                 : "=r"(r[0]), "=r"(r[1]), "=r"(r[2]), "=r"(r[3]) : "r"(addr));
}
__device__ __forceinline__ void mma16816f16(float* c, const uint32_t* a, const uint32_t* b) {
    asm volatile(
        "mma.sync.aligned.m16n8k16.row.col.f32.f16.f16.f32 "
        "{%0,%1,%2,%3}, {%4,%5,%6,%7}, {%8,%9}, {%0,%1,%2,%3};"
        : "+f"(c[0]), "+f"(c[1]), "+f"(c[2]), "+f"(c[3])
        : "r"(a[0]), "r"(a[1]), "r"(a[2]), "r"(a[3]), "r"(b[0]), "r"(b[1]));
}

// ---------------- scratch (static __device__, no allocs) --------------------
static __device__ __align__(16) unsigned char g_Xh[33554432];  // 64 mt * 32 ch * 16KB
static __device__ __align__(16) unsigned char g_Wh[8388608];   // 16 nt * 32 ch * 16KB

// ---------------- launch 0: X -> fp16 pre-swizzled tiles (verified) ----------
__global__ void conv_X(const float* __restrict__ x, unsigned char* __restrict__ Xh)
{
    int idx = blockIdx.x * blockDim.x + threadIdx.x;   // < 8192*256
    int m = idx >> 8;
    int k0 = (idx & 255) * 8;
    const float* row = x + (size_t)m * 2048 + k0;
    float4 v0 = *(const float4*)row;
    float4 v1 = *(const float4*)(row + 4);
    uint32_t off = (uint32_t)(((m >> 7) * 32 + (k0 >> 6)) << 14) + swz((m & 127) * 128 + (k0 & 63) * 2);
    uint4 pk;
    pk.x = h2u(__floats2half2_rn(v0.x, v0.y));
    pk.y = h2u(__floats2half2_rn(v0.z, v0.w));
    pk.z = h2u(__floats2half2_rn(v1.x, v1.y));
    pk.w = h2u(__floats2half2_rn(v1.z, v1.w));
    *(uint4*)(Xh + off) = pk;
}

// ---------------- launch 1: W_all (grid 128, one jh per block; R12 verbatim) -
__global__ void W_all(const float* __restrict__ p0, const float* __restrict__ p1,
                      const float* __restrict__ p2, const float* __restrict__ p3,
                      const float* __restrict__ p4, const float* __restrict__ p5,
                      const float* __restrict__ p6, const float* __restrict__ p7,
                      const float* __restrict__ p8, unsigned char* __restrict__ Wh)
{
    __shared__ float BUF[12288];
    float* R0 = BUF;
    float* SC = BUF + 4096;
    float* LS = BUF + 10240;
    int t = threadIdx.x, jh = blockIdx.x;
    int j2 = jh >> 2;

    // ---- phase A: cores 0-2, only column j2 ----
    {
        float* s0 = SC;           // 1024
        float* cc = SC + 1024;    // 1024
        float* s1 = SC + 2048;    // 4096
        for (int i = t; i < 1024; i += 256) { s0[i] = p0[i]; cc[i] = p1[i]; }
        __syncthreads();
        {
            int idx = t;
            int b = idx & 1, j = (idx >> 1) & 7, a = (idx >> 4) & 1, d = idx >> 5;
            const float* sr = s0 + (d * 8 + j) * 16;
            int ab = a * 2 + b;
            float* o = s1 + ((d * 2 + a) * 16 + (j * 2 + b)) * 16;
            #pragma unroll
            for (int r = 0; r < 16; ++r) {
                float acc = 0.f;
                #pragma unroll
                for (int l = 0; l < 16; ++l) acc = fmaf(sr[l], cc[(ab * 16 + l) * 16 + r], acc);
                o[r] = acc;
            }
        }
        __syncthreads();
        for (int i = t; i < 1024; i += 256) cc[i] = p2[i];
        __syncthreads();
        {
            int jj = j2 >> 1, bb = j2 & 1;
            for (int i = t; i < 512; i += 256) {
                int d2o = i >> 4, r = i & 15;
                int d = d2o >> 1, a = d2o & 1;
                const float* sr = s1 + (d * 16 + jj) * 16;
                int ab = a * 2 + bb;
                float acc = 0.f;
                #pragma unroll
                for (int l = 0; l < 16; ++l) acc = fmaf(sr[l], cc[(ab * 16 + l) * 16 + r], acc);
                R0[i] = acc;
            }
        }
    }
    __syncthreads();

    // ---- phase B: cores 3,4 -> LS[r*128 + dh] ----
    {
        for (int i = t; i < 1024; i += 256) { SC[i] = p3[i]; SC[1024 + i] = p4[i]; }
        __syncthreads();
        float* T3 = SC + 2048;
        int b3 = (jh >> 1) & 1, b4 = jh & 1;
        for (int i = t; i < 1024; i += 256) {
            int d3 = i >> 4, r = i & 15;
            int a = d3 & 1, d2 = d3 >> 1;
            float acc = 0.f;
            #pragma unroll
            for (int l = 0; l < 16; ++l)
                acc = fmaf(R0[d2 * 16 + l], SC[((a * 2 + b3) * 16 + l) * 16 + r], acc);
            T3[i] = acc;
        }
        __syncthreads();
        for (int i = t; i < 2048; i += 256) {
            int dh = i & 127, r = i >> 7;
            int a = dh & 1, d3 = dh >> 1;
            float acc = 0.f;
            #pragma unroll
            for (int l = 0; l < 16; ++l)
                acc = fmaf(T3[d3 * 16 + l], SC[1024 + ((a * 2 + b4) * 16 + l) * 16 + r], acc);
            LS[i] = acc;
        }
    }
    __syncthreads();

    // ---- phase C: R from cores 8,7,6,5 ----
    {
        float* S = SC;
        float* T = R0;
        if (t < 64) { int l = t >> 2, d = (t >> 1) & 1, jj = t & 1; S[l * 4 + d * 2 + jj] = p8[(d * 2 + jj) * 16 + l]; }
        __syncthreads();
        if (t < 256) {
            int l = t >> 4, dp = (t >> 2) & 3, jp = t & 3;
            int a = dp >> 1, d = dp & 1, bb = jp >> 1, jj = jp & 1;
            float acc = 0.f;
            #pragma unroll
            for (int r = 0; r < 16; ++r) acc = fmaf(p7[((a * 2 + bb) * 16 + r) * 16 + l], S[r * 4 + d * 2 + jj], acc);
            T[l * 16 + dp * 4 + jp] = acc;
        }
        __syncthreads();
        for (int i = t; i < 1024; i += 256) {
            int l = i >> 6, dp = (i >> 3) & 7, jp = i & 7;
            int a = dp >> 2, d = dp & 3, bb = jp >> 2, jj = jp & 3;
            float acc = 0.f;
            #pragma unroll
            for (int r = 0; r < 16; ++r) acc = fmaf(p6[((a * 2 + bb) * 16 + l) * 16 + r], T[r * 16 + d * 4 + jj], acc);
            S[l * 64 + dp * 8 + jp] = acc;
        }
        __syncthreads();
        for (int i = t; i < 4096; i += 256) {
            int l = i >> 8, dp = (i >> 4) & 15, jp = i & 15;
            int a = dp >> 3, d = dp & 7, bb = jp >> 3, jj = jp & 7;
            float acc = 0.f;
            #pragma unroll
            for (int r = 0; r < 16; ++r) acc = fmaf(p5[((a * 2 + bb) * 16 + l) * 16 + r], S[r * 64 + d * 8 + jj], acc);
            T[i] = acc;
        }
    }
    __syncthreads();

    // ---- phase D: combine + quantize + pre-swizzled store ----
    int dh = t >> 1;
    for (int jl = 0; jl < 16; ++jl) {
        int j = jh * 16 + jl;
        __half h[8];
        #pragma unroll
        for (int i = 0; i < 8; ++i) {
            int dl = (t & 1) * 8 + i;
            float acc = 0.f;
            #pragma unroll
            for (int r = 0; r < 16; ++r)
                acc = fmaf(LS[r * 128 + dh], R0[r * 256 + dl * 16 + jl], acc);
            h[i] = __float2half_rn(acc * 0.00390625f);
        }
        uint4 pk;
        pk.x = pack2h(h[0], h[1]);
        pk.y = pack2h(h[2], h[3]);
        pk.z = pack2h(h[4], h[5]);
        pk.w = pack2h(h[6], h[7]);
        uint32_t off = (uint32_t)(((j >> 7) * 32 + ((t * 8) >> 6)) << 14)
                     + swz((j & 127) * 128 + ((t * 8) & 63) * 2);
        *(uint4*)(Wh + off) = pk;
    }
}

// ---------------- launch 2: fp16 GEMM (micro-optimized) ----------------------
static constexpr int GSTAGES = 3;
static constexpr int STAGE_BYTES = 32768;
static constexpr uint32_t GEMM_SMEM = GSTAGES * STAGE_BYTES;

__device__ __forceinline__ void issue_stage(uint32_t sb, int buf, int ck, int tid,
                                            const unsigned char* __restrict__ Xh,
                                            const unsigned char* __restrict__ Wh,
                                            int by, int bx)
{
    const unsigned char* as = Xh + (((size_t)by * 32 + ck) << 14) + tid * 16;
    const unsigned char* bs = Wh + (((size_t)bx * 32 + ck) << 14) + tid * 16;
    uint32_t dst = sb + buf * STAGE_BYTES + tid * 16;
    #pragma unroll
    for (int i = 0; i < 4; ++i) cp16(dst + i * 4096, as + i * 4096);
    #pragma unroll
    for (int i = 0; i < 4; ++i) cp16(dst + 16384 + i * 4096, bs + i * 4096);
}

__global__ void __launch_bounds__(256, 2)
tt_gemm_f16(const unsigned char* __restrict__ Xh, const unsigned char* __restrict__ Wh,
            float* __restrict__ out)
{
    extern __shared__ unsigned char smem[];
    uint32_t sb = smem_u32(smem);
    int tid = threadIdx.x, wid = tid >> 5, lane = tid & 31;
    int bx = blockIdx.x, by = blockIdx.y;

    int wm = (wid & 1) * 64;
    int wn = (wid >> 1) * 32;
    int arow = wm + (lane & 15);
    int akb  = (lane >> 4) * 16;
    // B via ldsm_x4: lane pattern covers 16 rows (two 8-row blocks) x 2 k-halves
    int brow4 = wn + ((lane >> 4) & 1) * 8 + (lane & 7);
    int bkb   = ((lane >> 3) & 1) * 16;

    float acc[4][4][4];
    #pragma unroll
    for (int mi = 0; mi < 4; ++mi)
        #pragma unroll
        for (int ni = 0; ni < 4; ++ni)
            #pragma unroll
            for (int q = 0; q < 4; ++q) acc[mi][ni][q] = 0.f;

    issue_stage(sb, 0, 0, tid, Xh, Wh, by, bx); cp_commit();
    issue_stage(sb, 1, 1, tid, Xh, Wh, by, bx); cp_commit();

    // one k-chunk step with static stage base; issues next stage after ks=0
    auto step = [&](int it, uint32_t base, uint32_t nbuf) {
        cp_wait<GSTAGES - 2>();
        __syncthreads();

        #pragma unroll
        for (int ks = 0; ks < 4; ++ks) {
            uint32_t af[4][4], bf[4][2];
            #pragma unroll
            for (int mi = 0; mi < 4; ++mi)
                ldsm_x4(af[mi], base + swz((uint32_t)((arow + mi * 16) * 128 + ks * 32 + akb)));
            #pragma unroll
            for (int blk = 0; blk < 2; ++blk) {
                uint32_t tmp[4];
                ldsm_x4(tmp, base + 16384 + swz((uint32_t)((brow4 + blk * 16) * 128 + ks * 32 + bkb)));
                bf[2 * blk][0] = tmp[0]; bf[2 * blk][1] = tmp[1];
                bf[2 * blk + 1][0] = tmp[2]; bf[2 * blk + 1][1] = tmp[3];
            }
            #pragma unroll
            for (int mi = 0; mi < 4; ++mi)
                #pragma unroll
                for (int ni = 0; ni < 4; ++ni)
                    mma16816f16(acc[mi][ni], af[mi], bf[ni]);

            if (ks == 0) {   // off the barrier-exit critical path
                int nxt = it + 2;
                if (nxt < 32) issue_stage(sb, nbuf, nxt, tid, Xh, Wh, by, bx);
                cp_commit();
            }
        }
    };

    #pragma unroll 1
    for (int it = 0; it < 30; it += 3) {
        step(it,     sb,                   2);
        step(it + 1, sb + STAGE_BYTES,     0);
        step(it + 2, sb + 2 * STAGE_BYTES, 1);
    }
    step(30, sb, 2);
    step(31, sb + STAGE_BYTES, 0);

    int m0 = by * 128 + wm + (lane >> 2);
    int n0 = bx * 128 + wn + (lane & 3) * 2;
    #pragma unroll
    for (int mi = 0; mi < 4; ++mi) {
        #pragma unroll
        for (int ni = 0; ni < 4; ++ni) {
            float* p = out + (size_t)(m0 + mi * 16) * 2048 + n0 + ni * 8;
            *(float2*)p = make_float2(acc[mi][ni][0] * 256.f, acc[mi][ni][1] * 256.f);
            *(float2*)(p + 8 * 2048) = make_float2(acc[mi][ni][2] * 256.f, acc[mi][ni][3] * 256.f);
        }
    }
}

// ---------------- launch ------------------------------------------------------
extern "C" void kernel_launch(void* const* d_in, const int* in_sizes, int n_in,
                              void* d_out, int out_size)
{
    (void)in_sizes; (void)n_in; (void)out_size;
    const float* x = (const float*)d_in[0];
    const float* p[9];
    for (int i = 0; i < 9; ++i) p[i] = (const float*)d_in[1 + i];

    unsigned char *Xh, *Wh;
    cudaGetSymbolAddress((void**)&Xh, g_Xh);
    cudaGetSymbolAddress((void**)&Wh, g_Wh);

    conv_X<<<8192, 256>>>(x, Xh);                                            // 0
    W_all<<<128, 256>>>(p[0], p[1], p[2], p[3], p[4],
                        p[5], p[6], p[7], p[8], Wh);                         // 1
    cudaFuncSetAttribute(tt_gemm_f16, cudaFuncAttributeMaxDynamicSharedMemorySize, GEMM_SMEM);
    tt_gemm_f16<<<dim3(16, 64), 256, GEMM_SMEM>>>(Xh, Wh, (float*)d_out);    // 2
}

// round 15
// speedup vs baseline: 1.0897x; 1.0105x over previous
#include <cuda_runtime.h>
#include <cuda_fp16.h>
#include <cstdint>

// ===========================================================================
// TensorTrainProjection via dense operator + single fp16 tensor-core GEMM.
//   W[d,j] = TT-contraction of 9 cores (2048 x 2048)
//   out = X @ W,  X: [8192, 2048] fp32
// fp16 GEMM (K=2048), W stored * 2^-8 (exact), epilogue * 256.
// Round-15: R14 (203.3us) + GEMM issue-pressure spreading:
//   - A-half prefetch after ks=0, B-half after ks=1 (LSU burst split)
//   - pointer-increment addressing in the prefetch (no per-issue IMADs)
// ===========================================================================

__device__ __forceinline__ uint32_t smem_u32(const void* p) {
    uint32_t a;
    asm("{ .reg .u64 t; cvta.to.shared.u64 t, %1; cvt.u32.u64 %0, t; }" : "=r"(a) : "l"(p));
    return a;
}
__device__ __forceinline__ uint32_t swz(uint32_t o) { return o ^ ((o >> 3) & 0x70); }

__device__ __forceinline__ uint32_t h2u(__half2 v) {
    return (uint32_t)__half_as_ushort(__low2half(v)) |
           ((uint32_t)__half_as_ushort(__high2half(v)) << 16);
}
__device__ __forceinline__ uint32_t pack2h(__half a, __half b) {
    return (uint32_t)__half_as_ushort(a) | ((uint32_t)__half_as_ushort(b) << 16);
}

__device__ __forceinline__ void cp16(uint32_t dst, const void* src) {
    asm volatile("cp.async.cg.shared.global [%0], [%1], 16;" :: "r"(dst), "l"(src) : "memory");
}
__device__ __forceinline__ void cp_commit() { asm volatile("cp.async.commit_group;" ::: "memory"); }
template <int N>
__device__ __forceinline__ void cp_wait() { asm volatile("cp.async.wait_group %0;" :: "n"(N) : "memory"); }

__device__ __forceinline__ void ldsm_x4(uint32_t* r, uint32_t addr) {
    asm volatile("ldmatrix.sync.aligned.m8n8.x4.shared.b16 {%0,%1,%2,%3}, [%4];"
                 : "=r"(r[0]), "=r"(r[1]), "=r"(r[2]), "=r"(r[3]) : "r"(addr));
}
__device__ __forceinline__ void mma16816f16(float* c, const uint32_t* a, const uint32_t* b) {
    asm volatile(
        "mma.sync.aligned.m16n8k16.row.col.f32.f16.f16.f32 "
        "{%0,%1,%2,%3}, {%4,%5,%6,%7}, {%8,%9}, {%0,%1,%2,%3};"
        : "+f"(c[0]), "+f"(c[1]), "+f"(c[2]), "+f"(c[3])
        : "r"(a[0]), "r"(a[1]), "r"(a[2]), "r"(a[3]), "r"(b[0]), "r"(b[1]));
}

// ---------------- scratch (static __device__, no allocs) --------------------
static __device__ __align__(16) unsigned char g_Xh[33554432];  // 64 mt * 32 ch * 16KB
static __device__ __align__(16) unsigned char g_Wh[8388608];   // 16 nt * 32 ch * 16KB

// ---------------- launch 0: X -> fp16 pre-swizzled tiles (verified) ----------
__global__ void conv_X(const float* __restrict__ x, unsigned char* __restrict__ Xh)
{
    int idx = blockIdx.x * blockDim.x + threadIdx.x;   // < 8192*256
    int m = idx >> 8;
    int k0 = (idx & 255) * 8;
    const float* row = x + (size_t)m * 2048 + k0;
    float4 v0 = *(const float4*)row;
    float4 v1 = *(const float4*)(row + 4);
    uint32_t off = (uint32_t)(((m >> 7) * 32 + (k0 >> 6)) << 14) + swz((m & 127) * 128 + (k0 & 63) * 2);
    uint4 pk;
    pk.x = h2u(__floats2half2_rn(v0.x, v0.y));
    pk.y = h2u(__floats2half2_rn(v0.z, v0.w));
    pk.z = h2u(__floats2half2_rn(v1.x, v1.y));
    pk.w = h2u(__floats2half2_rn(v1.z, v1.w));
    *(uint4*)(Xh + off) = pk;
}

// ---------------- launch 1: W_all (grid 128, one jh per block; R12 verbatim) -
__global__ void W_all(const float* __restrict__ p0, const float* __restrict__ p1,
                      const float* __restrict__ p2, const float* __restrict__ p3,
                      const float* __restrict__ p4, const float* __restrict__ p5,
                      const float* __restrict__ p6, const float* __restrict__ p7,
                      const float* __restrict__ p8, unsigned char* __restrict__ Wh)
{
    __shared__ float BUF[12288];
    float* R0 = BUF;
    float* SC = BUF + 4096;
    float* LS = BUF + 10240;
    int t = threadIdx.x, jh = blockIdx.x;
    int j2 = jh >> 2;

    // ---- phase A: cores 0-2, only column j2 ----
    {
        float* s0 = SC;           // 1024
        float* cc = SC + 1024;    // 1024
        float* s1 = SC + 2048;    // 4096
        for (int i = t; i < 1024; i += 256) { s0[i] = p0[i]; cc[i] = p1[i]; }
        __syncthreads();
        {
            int idx = t;
            int b = idx & 1, j = (idx >> 1) & 7, a = (idx >> 4) & 1, d = idx >> 5;
            const float* sr = s0 + (d * 8 + j) * 16;
            int ab = a * 2 + b;
            float* o = s1 + ((d * 2 + a) * 16 + (j * 2 + b)) * 16;
            #pragma unroll
            for (int r = 0; r < 16; ++r) {
                float acc = 0.f;
                #pragma unroll
                for (int l = 0; l < 16; ++l) acc = fmaf(sr[l], cc[(ab * 16 + l) * 16 + r], acc);
                o[r] = acc;
            }
        }
        __syncthreads();
        for (int i = t; i < 1024; i += 256) cc[i] = p2[i];
        __syncthreads();
        {
            int jj = j2 >> 1, bb = j2 & 1;
            for (int i = t; i < 512; i += 256) {
                int d2o = i >> 4, r = i & 15;
                int d = d2o >> 1, a = d2o & 1;
                const float* sr = s1 + (d * 16 + jj) * 16;
                int ab = a * 2 + bb;
                float acc = 0.f;
                #pragma unroll
                for (int l = 0; l < 16; ++l) acc = fmaf(sr[l], cc[(ab * 16 + l) * 16 + r], acc);
                R0[i] = acc;
            }
        }
    }
    __syncthreads();

    // ---- phase B: cores 3,4 -> LS[r*128 + dh] ----
    {
        for (int i = t; i < 1024; i += 256) { SC[i] = p3[i]; SC[1024 + i] = p4[i]; }
        __syncthreads();
        float* T3 = SC + 2048;
        int b3 = (jh >> 1) & 1, b4 = jh & 1;
        for (int i = t; i < 1024; i += 256) {
            int d3 = i >> 4, r = i & 15;
            int a = d3 & 1, d2 = d3 >> 1;
            float acc = 0.f;
            #pragma unroll
            for (int l = 0; l < 16; ++l)
                acc = fmaf(R0[d2 * 16 + l], SC[((a * 2 + b3) * 16 + l) * 16 + r], acc);
            T3[i] = acc;
        }
        __syncthreads();
        for (int i = t; i < 2048; i += 256) {
            int dh = i & 127, r = i >> 7;
            int a = dh & 1, d3 = dh >> 1;
            float acc = 0.f;
            #pragma unroll
            for (int l = 0; l < 16; ++l)
                acc = fmaf(T3[d3 * 16 + l], SC[1024 + ((a * 2 + b4) * 16 + l) * 16 + r], acc);
            LS[i] = acc;
        }
    }
    __syncthreads();

    // ---- phase C: R from cores 8,7,6,5 ----
    {
        float* S = SC;
        float* T = R0;
        if (t < 64) { int l = t >> 2, d = (t >> 1) & 1, jj = t & 1; S[l * 4 + d * 2 + jj] = p8[(d * 2 + jj) * 16 + l]; }
        __syncthreads();
        if (t < 256) {
            int l = t >> 4, dp = (t >> 2) & 3, jp = t & 3;
            int a = dp >> 1, d = dp & 1, bb = jp >> 1, jj = jp & 1;
            float acc = 0.f;
            #pragma unroll
            for (int r = 0; r < 16; ++r) acc = fmaf(p7[((a * 2 + bb) * 16 + r) * 16 + l], S[r * 4 + d * 2 + jj], acc);
            T[l * 16 + dp * 4 + jp] = acc;
        }
        __syncthreads();
        for (int i = t; i < 1024; i += 256) {
            int l = i >> 6, dp = (i >> 3) & 7, jp = i & 7;
            int a = dp >> 2, d = dp & 3, bb = jp >> 2, jj = jp & 3;
            float acc = 0.f;
            #pragma unroll
            for (int r = 0; r < 16; ++r) acc = fmaf(p6[((a * 2 + bb) * 16 + l) * 16 + r], T[r * 16 + d * 4 + jj], acc);
            S[l * 64 + dp * 8 + jp] = acc;
        }
        __syncthreads();
        for (int i = t; i < 4096; i += 256) {
            int l = i >> 8, dp = (i >> 4) & 15, jp = i & 15;
            int a = dp >> 3, d = dp & 7, bb = jp >> 3, jj = jp & 7;
            float acc = 0.f;
            #pragma unroll
            for (int r = 0; r < 16; ++r) acc = fmaf(p5[((a * 2 + bb) * 16 + l) * 16 + r], S[r * 64 + d * 8 + jj], acc);
            T[i] = acc;
        }
    }
    __syncthreads();

    // ---- phase D: combine + quantize + pre-swizzled store ----
    int dh = t >> 1;
    for (int jl = 0; jl < 16; ++jl) {
        int j = jh * 16 + jl;
        __half h[8];
        #pragma unroll
        for (int i = 0; i < 8; ++i) {
            int dl = (t & 1) * 8 + i;
            float acc = 0.f;
            #pragma unroll
            for (int r = 0; r < 16; ++r)
                acc = fmaf(LS[r * 128 + dh], R0[r * 256 + dl * 16 + jl], acc);
            h[i] = __float2half_rn(acc * 0.00390625f);
        }
        uint4 pk;
        pk.x = pack2h(h[0], h[1]);
        pk.y = pack2h(h[2], h[3]);
        pk.z = pack2h(h[4], h[5]);
        pk.w = pack2h(h[6], h[7]);
        uint32_t off = (uint32_t)(((j >> 7) * 32 + ((t * 8) >> 6)) << 14)
                     + swz((j & 127) * 128 + ((t * 8) & 63) * 2);
        *(uint4*)(Wh + off) = pk;
    }
}

// ---------------- launch 2: fp16 GEMM (issue-pressure spread) ----------------
static constexpr int GSTAGES = 3;
static constexpr int STAGE_BYTES = 32768;
static constexpr uint32_t GEMM_SMEM = GSTAGES * STAGE_BYTES;

__global__ void __launch_bounds__(256, 2)
tt_gemm_f16(const unsigned char* __restrict__ Xh, const unsigned char* __restrict__ Wh,
            float* __restrict__ out)
{
    extern __shared__ unsigned char smem[];
    uint32_t sb = smem_u32(smem);
    int tid = threadIdx.x, wid = tid >> 5, lane = tid & 31;
    int bx = blockIdx.x, by = blockIdx.y;

    int wm = (wid & 1) * 64;
    int wn = (wid >> 1) * 32;
    int arow = wm + (lane & 15);
    int akb  = (lane >> 4) * 16;
    int brow4 = wn + ((lane >> 4) & 1) * 8 + (lane & 7);
    int bkb   = ((lane >> 3) & 1) * 16;

    // pointer-increment prefetch state (advance by 16KB per chunk)
    const unsigned char* aptr = Xh + (((size_t)by * 32) << 14) + tid * 16;
    const unsigned char* bptr = Wh + (((size_t)bx * 32) << 14) + tid * 16;
    uint32_t dA = sb + tid * 16;
    uint32_t dB = sb + 16384 + tid * 16;

    auto issueA = [&](uint32_t buf, int ck) {
        const unsigned char* s = aptr + ((size_t)ck << 14);
        uint32_t d = dA + buf * STAGE_BYTES;
        #pragma unroll
        for (int i = 0; i < 4; ++i) cp16(d + i * 4096, s + i * 4096);
    };
    auto issueB = [&](uint32_t buf, int ck) {
        const unsigned char* s = bptr + ((size_t)ck << 14);
        uint32_t d = dB + buf * STAGE_BYTES;
        #pragma unroll
        for (int i = 0; i < 4; ++i) cp16(d + i * 4096, s + i * 4096);
    };

    float acc[4][4][4];
    #pragma unroll
    for (int mi = 0; mi < 4; ++mi)
        #pragma unroll
        for (int ni = 0; ni < 4; ++ni)
            #pragma unroll
            for (int q = 0; q < 4; ++q) acc[mi][ni][q] = 0.f;

    issueA(0, 0); issueB(0, 0); cp_commit();
    issueA(1, 1); issueB(1, 1); cp_commit();

    // one k-chunk step; A prefetch after ks=0, B prefetch+commit after ks=1
    auto step = [&](int it, uint32_t base, uint32_t nbuf) {
        cp_wait<GSTAGES - 2>();
        __syncthreads();
        int nxt = it + 2;

        #pragma unroll
        for (int ks = 0; ks < 4; ++ks) {
            uint32_t af[4][4], bf[4][2];
            #pragma unroll
            for (int mi = 0; mi < 4; ++mi)
                ldsm_x4(af[mi], base + swz((uint32_t)((arow + mi * 16) * 128 + ks * 32 + akb)));
            #pragma unroll
            for (int blk = 0; blk < 2; ++blk) {
                uint32_t tmp[4];
                ldsm_x4(tmp, base + 16384 + swz((uint32_t)((brow4 + blk * 16) * 128 + ks * 32 + bkb)));
                bf[2 * blk][0] = tmp[0]; bf[2 * blk][1] = tmp[1];
                bf[2 * blk + 1][0] = tmp[2]; bf[2 * blk + 1][1] = tmp[3];
            }
            #pragma unroll
            for (int mi = 0; mi < 4; ++mi)
                #pragma unroll
                for (int ni = 0; ni < 4; ++ni)
                    mma16816f16(acc[mi][ni], af[mi], bf[ni]);

            if (ks == 0 && nxt < 32) issueA(nbuf, nxt);
            if (ks == 1) {
                if (nxt < 32) issueB(nbuf, nxt);
                cp_commit();
            }
        }
    };

    #pragma unroll 1
    for (int it = 0; it < 30; it += 3) {
        step(it,     sb,                   2);
        step(it + 1, sb + STAGE_BYTES,     0);
        step(it + 2, sb + 2 * STAGE_BYTES, 1);
    }
    step(30, sb, 2);
    step(31, sb + STAGE_BYTES, 0);

    int m0 = by * 128 + wm + (lane >> 2);
    int n0 = bx * 128 + wn + (lane & 3) * 2;
    #pragma unroll
    for (int mi = 0; mi < 4; ++mi) {
        #pragma unroll
        for (int ni = 0; ni < 4; ++ni) {
            float* p = out + (size_t)(m0 + mi * 16) * 2048 + n0 + ni * 8;
            *(float2*)p = make_float2(acc[mi][ni][0] * 256.f, acc[mi][ni][1] * 256.f);
            *(float2*)(p + 8 * 2048) = make_float2(acc[mi][ni][2] * 256.f, acc[mi][ni][3] * 256.f);
        }
    }
}

// ---------------- launch ------------------------------------------------------
extern "C" void kernel_launch(void* const* d_in, const int* in_sizes, int n_in,
                              void* d_out, int out_size)
{
    (void)in_sizes; (void)n_in; (void)out_size;
    const float* x = (const float*)d_in[0];
    const float* p[9];
    for (int i = 0; i < 9; ++i) p[i] = (const float*)d_in[1 + i];

    unsigned char *Xh, *Wh;
    cudaGetSymbolAddress((void**)&Xh, g_Xh);
    cudaGetSymbolAddress((void**)&Wh, g_Wh);

    conv_X<<<8192, 256>>>(x, Xh);                                            // 0
    W_all<<<128, 256>>>(p[0], p[1], p[2], p[3], p[4],
                        p[5], p[6], p[7], p[8], Wh);                         // 1
    cudaFuncSetAttribute(tt_gemm_f16, cudaFuncAttributeMaxDynamicSharedMemorySize, GEMM_SMEM);
    tt_gemm_f16<<<dim3(16, 64), 256, GEMM_SMEM>>>(Xh, Wh, (float*)d_out);    // 2
}

// round 16
// speedup vs baseline: 1.1007x; 1.0101x over previous
#include <cuda_runtime.h>
#include <cuda_fp16.h>
#include <cstdint>

// ===========================================================================
// TensorTrainProjection via dense operator + single fp16 tensor-core GEMM.
//   W[d,j] = TT-contraction of 9 cores (2048 x 2048)
//   out = X @ W,  X: [8192, 2048] fp32
// fp16 GEMM (K=2048), W stored * 2^-8 (exact), epilogue * 256.
// Round-16: R15 (201.2us) + finest prefetch spread: 2 cp16 per ks phase
// (A halves after ks0/ks1, B halves after ks2/ks3, commit after ks3).
// Same group structure -> identical pipeline semantics, only issue placement.
// ===========================================================================

__device__ __forceinline__ uint32_t smem_u32(const void* p) {
    uint32_t a;
    asm("{ .reg .u64 t; cvta.to.shared.u64 t, %1; cvt.u32.u64 %0, t; }" : "=r"(a) : "l"(p));
    return a;
}
__device__ __forceinline__ uint32_t swz(uint32_t o) { return o ^ ((o >> 3) & 0x70); }

__device__ __forceinline__ uint32_t h2u(__half2 v) {
    return (uint32_t)__half_as_ushort(__low2half(v)) |
           ((uint32_t)__half_as_ushort(__high2half(v)) << 16);
}
__device__ __forceinline__ uint32_t pack2h(__half a, __half b) {
    return (uint32_t)__half_as_ushort(a) | ((uint32_t)__half_as_ushort(b) << 16);
}

__device__ __forceinline__ void cp16(uint32_t dst, const void* src) {
    asm volatile("cp.async.cg.shared.global [%0], [%1], 16;" :: "r"(dst), "l"(src) : "memory");
}
__device__ __forceinline__ void cp_commit() { asm volatile("cp.async.commit_group;" ::: "memory"); }
template <int N>
__device__ __forceinline__ void cp_wait() { asm volatile("cp.async.wait_group %0;" :: "n"(N) : "memory"); }

__device__ __forceinline__ void ldsm_x4(uint32_t* r, uint32_t addr) {
    asm volatile("ldmatrix.sync.aligned.m8n8.x4.shared.b16 {%0,%1,%2,%3}, [%4];"
                 : "=r"(r[0]), "=r"(r[1]), "=r"(r[2]), "=r"(r[3]) : "r"(addr));
}
__device__ __forceinline__ void mma16816f16(float* c, const uint32_t* a, const uint32_t* b) {
    asm volatile(
        "mma.sync.aligned.m16n8k16.row.col.f32.f16.f16.f32 "
        "{%0,%1,%2,%3}, {%4,%5,%6,%7}, {%8,%9}, {%0,%1,%2,%3};"
        : "+f"(c[0]), "+f"(c[1]), "+f"(c[2]), "+f"(c[3])
        : "r"(a[0]), "r"(a[1]), "r"(a[2]), "r"(a[3]), "r"(b[0]), "r"(b[1]));
}

// ---------------- scratch (static __device__, no allocs) --------------------
static __device__ __align__(16) unsigned char g_Xh[33554432];  // 64 mt * 32 ch * 16KB
static __device__ __align__(16) unsigned char g_Wh[8388608];   // 16 nt * 32 ch * 16KB

// ---------------- launch 0: X -> fp16 pre-swizzled tiles (verified) ----------
__global__ void conv_X(const float* __restrict__ x, unsigned char* __restrict__ Xh)
{
    int idx = blockIdx.x * blockDim.x + threadIdx.x;   // < 8192*256
    int m = idx >> 8;
    int k0 = (idx & 255) * 8;
    const float* row = x + (size_t)m * 2048 + k0;
    float4 v0 = *(const float4*)row;
    float4 v1 = *(const float4*)(row + 4);
    uint32_t off = (uint32_t)(((m >> 7) * 32 + (k0 >> 6)) << 14) + swz((m & 127) * 128 + (k0 & 63) * 2);
    uint4 pk;
    pk.x = h2u(__floats2half2_rn(v0.x, v0.y));
    pk.y = h2u(__floats2half2_rn(v0.z, v0.w));
    pk.z = h2u(__floats2half2_rn(v1.x, v1.y));
    pk.w = h2u(__floats2half2_rn(v1.z, v1.w));
    *(uint4*)(Xh + off) = pk;
}

// ---------------- launch 1: W_all (grid 128, one jh per block; R12 verbatim) -
__global__ void W_all(const float* __restrict__ p0, const float* __restrict__ p1,
                      const float* __restrict__ p2, const float* __restrict__ p3,
                      const float* __restrict__ p4, const float* __restrict__ p5,
                      const float* __restrict__ p6, const float* __restrict__ p7,
                      const float* __restrict__ p8, unsigned char* __restrict__ Wh)
{
    __shared__ float BUF[12288];
    float* R0 = BUF;
    float* SC = BUF + 4096;
    float* LS = BUF + 10240;
    int t = threadIdx.x, jh = blockIdx.x;
    int j2 = jh >> 2;

    // ---- phase A: cores 0-2, only column j2 ----
    {
        float* s0 = SC;           // 1024
        float* cc = SC + 1024;    // 1024
        float* s1 = SC + 2048;    // 4096
        for (int i = t; i < 1024; i += 256) { s0[i] = p0[i]; cc[i] = p1[i]; }
        __syncthreads();
        {
            int idx = t;
            int b = idx & 1, j = (idx >> 1) & 7, a = (idx >> 4) & 1, d = idx >> 5;
            const float* sr = s0 + (d * 8 + j) * 16;
            int ab = a * 2 + b;
            float* o = s1 + ((d * 2 + a) * 16 + (j * 2 + b)) * 16;
            #pragma unroll
            for (int r = 0; r < 16; ++r) {
                float acc = 0.f;
                #pragma unroll
                for (int l = 0; l < 16; ++l) acc = fmaf(sr[l], cc[(ab * 16 + l) * 16 + r], acc);
                o[r] = acc;
            }
        }
        __syncthreads();
        for (int i = t; i < 1024; i += 256) cc[i] = p2[i];
        __syncthreads();
        {
            int jj = j2 >> 1, bb = j2 & 1;
            for (int i = t; i < 512; i += 256) {
                int d2o = i >> 4, r = i & 15;
                int d = d2o >> 1, a = d2o & 1;
                const float* sr = s1 + (d * 16 + jj) * 16;
                int ab = a * 2 + bb;
                float acc = 0.f;
                #pragma unroll
                for (int l = 0; l < 16; ++l) acc = fmaf(sr[l], cc[(ab * 16 + l) * 16 + r], acc);
                R0[i] = acc;
            }
        }
    }
    __syncthreads();

    // ---- phase B: cores 3,4 -> LS[r*128 + dh] ----
    {
        for (int i = t; i < 1024; i += 256) { SC[i] = p3[i]; SC[1024 + i] = p4[i]; }
        __syncthreads();
        float* T3 = SC + 2048;
        int b3 = (jh >> 1) & 1, b4 = jh & 1;
        for (int i = t; i < 1024; i += 256) {
            int d3 = i >> 4, r = i & 15;
            int a = d3 & 1, d2 = d3 >> 1;
            float acc = 0.f;
            #pragma unroll
            for (int l = 0; l < 16; ++l)
                acc = fmaf(R0[d2 * 16 + l], SC[((a * 2 + b3) * 16 + l) * 16 + r], acc);
            T3[i] = acc;
        }
        __syncthreads();
        for (int i = t; i < 2048; i += 256) {
            int dh = i & 127, r = i >> 7;
            int a = dh & 1, d3 = dh >> 1;
            float acc = 0.f;
            #pragma unroll
            for (int l = 0; l < 16; ++l)
                acc = fmaf(T3[d3 * 16 + l], SC[1024 + ((a * 2 + b4) * 16 + l) * 16 + r], acc);
            LS[i] = acc;
        }
    }
    __syncthreads();

    // ---- phase C: R from cores 8,7,6,5 ----
    {
        float* S = SC;
        float* T = R0;
        if (t < 64) { int l = t >> 2, d = (t >> 1) & 1, jj = t & 1; S[l * 4 + d * 2 + jj] = p8[(d * 2 + jj) * 16 + l]; }
        __syncthreads();
        if (t < 256) {
            int l = t >> 4, dp = (t >> 2) & 3, jp = t & 3;
            int a = dp >> 1, d = dp & 1, bb = jp >> 1, jj = jp & 1;
            float acc = 0.f;
            #pragma unroll
            for (int r = 0; r < 16; ++r) acc = fmaf(p7[((a * 2 + bb) * 16 + r) * 16 + l], S[r * 4 + d * 2 + jj], acc);
            T[l * 16 + dp * 4 + jp] = acc;
        }
        __syncthreads();
        for (int i = t; i < 1024; i += 256) {
            int l = i >> 6, dp = (i >> 3) & 7, jp = i & 7;
            int a = dp >> 2, d = dp & 3, bb = jp >> 2, jj = jp & 3;
            float acc = 0.f;
            #pragma unroll
            for (int r = 0; r < 16; ++r) acc = fmaf(p6[((a * 2 + bb) * 16 + l) * 16 + r], T[r * 16 + d * 4 + jj], acc);
            S[l * 64 + dp * 8 + jp] = acc;
        }
        __syncthreads();
        for (int i = t; i < 4096; i += 256) {
            int l = i >> 8, dp = (i >> 4) & 15, jp = i & 15;
            int a = dp >> 3, d = dp & 7, bb = jp >> 3, jj = jp & 7;
            float acc = 0.f;
            #pragma unroll
            for (int r = 0; r < 16; ++r) acc = fmaf(p5[((a * 2 + bb) * 16 + l) * 16 + r], S[r * 64 + d * 8 + jj], acc);
            T[i] = acc;
        }
    }
    __syncthreads();

    // ---- phase D: combine + quantize + pre-swizzled store ----
    int dh = t >> 1;
    for (int jl = 0; jl < 16; ++jl) {
        int j = jh * 16 + jl;
        __half h[8];
        #pragma unroll
        for (int i = 0; i < 8; ++i) {
            int dl = (t & 1) * 8 + i;
            float acc = 0.f;
            #pragma unroll
            for (int r = 0; r < 16; ++r)
                acc = fmaf(LS[r * 128 + dh], R0[r * 256 + dl * 16 + jl], acc);
            h[i] = __float2half_rn(acc * 0.00390625f);
        }
        uint4 pk;
        pk.x = pack2h(h[0], h[1]);
        pk.y = pack2h(h[2], h[3]);
        pk.z = pack2h(h[4], h[5]);
        pk.w = pack2h(h[6], h[7]);
        uint32_t off = (uint32_t)(((j >> 7) * 32 + ((t * 8) >> 6)) << 14)
                     + swz((j & 127) * 128 + ((t * 8) & 63) * 2);
        *(uint4*)(Wh + off) = pk;
    }
}

// ---------------- launch 2: fp16 GEMM (finest prefetch spread) ---------------
static constexpr int GSTAGES = 3;
static constexpr int STAGE_BYTES = 32768;
static constexpr uint32_t GEMM_SMEM = GSTAGES * STAGE_BYTES;

__global__ void __launch_bounds__(256, 2)
tt_gemm_f16(const unsigned char* __restrict__ Xh, const unsigned char* __restrict__ Wh,
            float* __restrict__ out)
{
    extern __shared__ unsigned char smem[];
    uint32_t sb = smem_u32(smem);
    int tid = threadIdx.x, wid = tid >> 5, lane = tid & 31;
    int bx = blockIdx.x, by = blockIdx.y;

    int wm = (wid & 1) * 64;
    int wn = (wid >> 1) * 32;
    int arow = wm + (lane & 15);
    int akb  = (lane >> 4) * 16;
    int brow4 = wn + ((lane >> 4) & 1) * 8 + (lane & 7);
    int bkb   = ((lane >> 3) & 1) * 16;

    const unsigned char* aptr = Xh + (((size_t)by * 32) << 14) + tid * 16;
    const unsigned char* bptr = Wh + (((size_t)bx * 32) << 14) + tid * 16;
    uint32_t dA = sb + tid * 16;
    uint32_t dB = sb + 16384 + tid * 16;

    // half = 0: chunks {0,1}*4KB ; half = 1: chunks {2,3}*4KB
    auto issueAh = [&](uint32_t buf, int ck, int half) {
        const unsigned char* s = aptr + ((size_t)ck << 14) + half * 8192;
        uint32_t d = dA + buf * STAGE_BYTES + half * 8192;
        cp16(d, s);
        cp16(d + 4096, s + 4096);
    };
    auto issueBh = [&](uint32_t buf, int ck, int half) {
        const unsigned char* s = bptr + ((size_t)ck << 14) + half * 8192;
        uint32_t d = dB + buf * STAGE_BYTES + half * 8192;
        cp16(d, s);
        cp16(d + 4096, s + 4096);
    };

    float acc[4][4][4];
    #pragma unroll
    for (int mi = 0; mi < 4; ++mi)
        #pragma unroll
        for (int ni = 0; ni < 4; ++ni)
            #pragma unroll
            for (int q = 0; q < 4; ++q) acc[mi][ni][q] = 0.f;

    issueAh(0, 0, 0); issueAh(0, 0, 1); issueBh(0, 0, 0); issueBh(0, 0, 1); cp_commit();
    issueAh(1, 1, 0); issueAh(1, 1, 1); issueBh(1, 1, 0); issueBh(1, 1, 1); cp_commit();

    // one k-chunk step; 2 cp16 per ks phase, commit after ks=3
    auto step = [&](int it, uint32_t base, uint32_t nbuf) {
        cp_wait<GSTAGES - 2>();
        __syncthreads();
        int nxt = it + 2;
        bool pf = nxt < 32;

        #pragma unroll
        for (int ks = 0; ks < 4; ++ks) {
            uint32_t af[4][4], bf[4][2];
            #pragma unroll
            for (int mi = 0; mi < 4; ++mi)
                ldsm_x4(af[mi], base + swz((uint32_t)((arow + mi * 16) * 128 + ks * 32 + akb)));
            #pragma unroll
            for (int blk = 0; blk < 2; ++blk) {
                uint32_t tmp[4];
                ldsm_x4(tmp, base + 16384 + swz((uint32_t)((brow4 + blk * 16) * 128 + ks * 32 + bkb)));
                bf[2 * blk][0] = tmp[0]; bf[2 * blk][1] = tmp[1];
                bf[2 * blk + 1][0] = tmp[2]; bf[2 * blk + 1][1] = tmp[3];
            }
            #pragma unroll
            for (int mi = 0; mi < 4; ++mi)
                #pragma unroll
                for (int ni = 0; ni < 4; ++ni)
                    mma16816f16(acc[mi][ni], af[mi], bf[ni]);

            if (ks == 0 && pf) issueAh(nbuf, nxt, 0);
            if (ks == 1 && pf) issueAh(nbuf, nxt, 1);
            if (ks == 2 && pf) { issueBh(nbuf, nxt, 0); issueBh(nbuf, nxt, 1); }
            if (ks == 3) cp_commit();
        }
    };

    #pragma unroll 1
    for (int it = 0; it < 30; it += 3) {
        step(it,     sb,                   2);
        step(it + 1, sb + STAGE_BYTES,     0);
        step(it + 2, sb + 2 * STAGE_BYTES, 1);
    }
    step(30, sb, 2);
    step(31, sb + STAGE_BYTES, 0);

    int m0 = by * 128 + wm + (lane >> 2);
    int n0 = bx * 128 + wn + (lane & 3) * 2;
    #pragma unroll
    for (int mi = 0; mi < 4; ++mi) {
        #pragma unroll
        for (int ni = 0; ni < 4; ++ni) {
            float* p = out + (size_t)(m0 + mi * 16) * 2048 + n0 + ni * 8;
            *(float2*)p = make_float2(acc[mi][ni][0] * 256.f, acc[mi][ni][1] * 256.f);
            *(float2*)(p + 8 * 2048) = make_float2(acc[mi][ni][2] * 256.f, acc[mi][ni][3] * 256.f);
        }
    }
}

// ---------------- launch ------------------------------------------------------
extern "C" void kernel_launch(void* const* d_in, const int* in_sizes, int n_in,
                              void* d_out, int out_size)
{
    (void)in_sizes; (void)n_in; (void)out_size;
    const float* x = (const float*)d_in[0];
    const float* p[9];
    for (int i = 0; i < 9; ++i) p[i] = (const float*)d_in[1 + i];

    unsigned char *Xh, *Wh;
    cudaGetSymbolAddress((void**)&Xh, g_Xh);
    cudaGetSymbolAddress((void**)&Wh, g_Wh);

    conv_X<<<8192, 256>>>(x, Xh);                                            // 0
    W_all<<<128, 256>>>(p[0], p[1], p[2], p[3], p[4],
                        p[5], p[6], p[7], p[8], Wh);                         // 1
    cudaFuncSetAttribute(tt_gemm_f16, cudaFuncAttributeMaxDynamicSharedMemorySize, GEMM_SMEM);
    tt_gemm_f16<<<dim3(16, 64), 256, GEMM_SMEM>>>(Xh, Wh, (float*)d_out);    // 2
}